// round 7
// baseline (speedup 1.0000x reference)
#include <cuda_runtime.h>
#include <cuda_bf16.h>
#include <cstdint>

// out[64,8192] = x[64,8192] @ blockdiag(blocks), 32 diagonal 256x256 blocks.
// R7: grid 256 = 32 blocks x 8 col-chunks of 32; 256 threads (8 warps) per CTA
// -> 2 CTAs/SM co-residency for cross-CTA latency hiding.
// Per CTA: out[0:64, col0:col0+32] = x[0:64, k0:k0+256] @ B[k0:k0+256, col0:col0+32]
// bf16 HMMA + 3-term split (xh@Bh + xh@Bl + xl@Bh), K in 4 chunks of 64,
// double-buffered smem; iteration order LDG -> compute -> STS -> sync.

#define NROW 8192

#define CHUNK_B  8192            // one bf16 buffer: 64 rows x 128B (B rows half-used)
#define OFF_AH   0
#define OFF_AL   16384
#define OFF_BH   32768
#define OFF_BL   49152
#define SMEM_BYTES 65536

__device__ __forceinline__ uint32_t smem_u32(const void* p) {
    uint32_t a;
    asm("{ .reg .u64 t; cvta.to.shared.u64 t, %1; cvt.u32.u64 %0, t; }" : "=r"(a) : "l"(p));
    return a;
}
__device__ __forceinline__ void ldsm_x4(uint32_t* r, uint32_t addr) {
    asm volatile("ldmatrix.sync.aligned.m8n8.x4.shared.b16 {%0,%1,%2,%3}, [%4];"
                 : "=r"(r[0]), "=r"(r[1]), "=r"(r[2]), "=r"(r[3]) : "r"(addr));
}
__device__ __forceinline__ void ldsm_x4_t(uint32_t* r, uint32_t addr) {
    asm volatile("ldmatrix.sync.aligned.m8n8.x4.trans.shared.b16 {%0,%1,%2,%3}, [%4];"
                 : "=r"(r[0]), "=r"(r[1]), "=r"(r[2]), "=r"(r[3]) : "r"(addr));
}
__device__ __forceinline__ void mma_bf16(float* d, const uint32_t* a, uint32_t b0, uint32_t b1) {
    asm volatile(
        "mma.sync.aligned.m16n8k16.row.col.f32.bf16.bf16.f32 "
        "{%0,%1,%2,%3}, {%4,%5,%6,%7}, {%8,%9}, {%0,%1,%2,%3};"
        : "+f"(d[0]), "+f"(d[1]), "+f"(d[2]), "+f"(d[3])
        : "r"(a[0]), "r"(a[1]), "r"(a[2]), "r"(a[3]), "r"(b0), "r"(b1));
}
__device__ __forceinline__ void split2(float a, float b, uint32_t& h, uint32_t& l) {
    __nv_bfloat162 hh = __floats2bfloat162_rn(a, b);
    float ra = a - __bfloat162float(hh.x);
    float rb = b - __bfloat162float(hh.y);
    __nv_bfloat162 ll = __floats2bfloat162_rn(ra, rb);
    h = *(uint32_t*)&hh;
    l = *(uint32_t*)&ll;
}

__global__ void __launch_bounds__(256, 2)
block_diag_hmma(const float* __restrict__ x,
                const float* __restrict__ blocks,
                float* __restrict__ out) {
    extern __shared__ char smem[];
    const uint32_t sbase = smem_u32(smem);

    const int tid   = threadIdx.x;
    const int wid   = tid >> 5;
    const int lid   = tid & 31;
    const int bx    = blockIdx.x;
    const int dblk  = bx >> 3;
    const int chunk = bx & 7;
    const int k0    = dblk * 256;
    const int col0  = k0 + chunk * 32;

    // ---- LDG one 64-k chunk into regs: A 4x float4, B 2x float4 ----
    auto ldgChunk = [&](int c, float4* ra, float4* rb) {
        const int kg = k0 + c * 64;
        #pragma unroll
        for (int p = 0; p < 4; ++p) {
            int idx = p * 256 + tid;
            int m = idx >> 4, sq = idx & 15;
            ra[p] = *(const float4*)(x + (size_t)m * NROW + kg + sq * 4);
        }
        #pragma unroll
        for (int p = 0; p < 2; ++p) {
            int idx = p * 256 + tid;
            int k = idx >> 3, n4 = idx & 7;
            rb[p] = *(const float4*)(blocks + (size_t)(kg + k) * NROW + col0 + n4 * 4);
        }
    };

    // ---- split + STS one chunk ----
    auto stsChunk = [&](int buf, const float4* ra, const float4* rb) {
        char* Ah = smem + OFF_AH + buf * CHUNK_B;
        char* Al = smem + OFF_AL + buf * CHUNK_B;
        char* Bh = smem + OFF_BH + buf * CHUNK_B;
        char* Bl = smem + OFF_BL + buf * CHUNK_B;
        uint32_t h01, l01, h23, l23;
        #pragma unroll
        for (int p = 0; p < 4; ++p) {
            int idx = p * 256 + tid;
            int m = idx >> 4, sq = idx & 15;
            uint32_t off = (uint32_t)(m * 128 + (((sq >> 1) ^ (m & 7)) * 16 + (sq & 1) * 8));
            split2(ra[p].x, ra[p].y, h01, l01);
            split2(ra[p].z, ra[p].w, h23, l23);
            *(uint2*)(Ah + off) = make_uint2(h01, h23);
            *(uint2*)(Al + off) = make_uint2(l01, l23);
        }
        #pragma unroll
        for (int p = 0; p < 2; ++p) {
            int idx = p * 256 + tid;
            int k = idx >> 3, n4 = idx & 7;
            uint32_t off = (uint32_t)(k * 128 + (((n4 >> 1) ^ (k & 7)) * 16 + (n4 & 1) * 8));
            split2(rb[p].x, rb[p].y, h01, l01);
            split2(rb[p].z, rb[p].w, h23, l23);
            *(uint2*)(Bh + off) = make_uint2(h01, h23);
            *(uint2*)(Bl + off) = make_uint2(l01, l23);
        }
    };

    // ---- compute setup: 8 warps = 4m x 2n, each 16x16 ----
    const int wm = wid & 3;
    const int wn = wid >> 2;
    const int m_base = wm * 16;
    const int n_base = wn * 16;

    const int a_row = m_base + (lid & 15);
    const int a_ch  = lid >> 4;
    const int a_rx  = a_row & 7;
    const uint32_t a_rowbase = (uint32_t)(a_row * 128);

    const int b_g   = (wn * 2 + (lid >> 4)) ^ (lid & 7);
    const uint32_t b_base = (uint32_t)((lid & 15) * 128 + b_g * 16);

    float acc[2][4] = {};

    auto computeChunk = [&](int buf) {
        const uint32_t aH = sbase + OFF_AH + buf * CHUNK_B;
        const uint32_t aL = sbase + OFF_AL + buf * CHUNK_B;
        const uint32_t bH = sbase + OFF_BH + buf * CHUNK_B;
        const uint32_t bL = sbase + OFF_BL + buf * CHUNK_B;
        uint32_t ah[4], al[4], bh[4], bl[4];
        #pragma unroll
        for (int ks = 0; ks < 4; ++ks) {
            uint32_t a_off = a_rowbase + (uint32_t)((((ks * 2 + a_ch) ^ a_rx)) * 16);
            uint32_t b_off = b_base + (uint32_t)(ks * 2048);
            ldsm_x4(ah, aH + a_off);
            ldsm_x4(al, aL + a_off);
            ldsm_x4_t(bh, bH + b_off);
            ldsm_x4_t(bl, bL + b_off);
            mma_bf16(acc[0], ah, bh[0], bh[1]);
            mma_bf16(acc[1], ah, bh[2], bh[3]);
            mma_bf16(acc[0], ah, bl[0], bl[1]);
            mma_bf16(acc[1], ah, bl[2], bl[3]);
            mma_bf16(acc[0], al, bh[0], bh[1]);
            mma_bf16(acc[1], al, bh[2], bh[3]);
        }
    };

    // ---- pipeline: LDG -> compute -> STS -> sync ----
    float4 rA[2][4], rB[2][2];
    ldgChunk(0, rA[0], rB[0]);
    stsChunk(0, rA[0], rB[0]);
    ldgChunk(1, rA[1], rB[1]);
    __syncthreads();

    #pragma unroll
    for (int c = 0; c < 4; ++c) {
        if (c < 2) ldgChunk(c + 2, rA[c & 1], rB[c & 1]);
        computeChunk(c & 1);
        if (c < 3) {
            stsChunk((c + 1) & 1, rA[(c + 1) & 1], rB[(c + 1) & 1]);
            __syncthreads();
        }
    }

    // ---- epilogue ----
    const int grp = lid >> 2;
    const int tc  = lid & 3;
    const int row0 = m_base + grp;
    const int row1 = row0 + 8;
    #pragma unroll
    for (int nh = 0; nh < 2; ++nh) {
        int col = col0 + n_base + nh * 8 + tc * 2;
        *(float2*)(out + (size_t)row0 * NROW + col) = make_float2(acc[nh][0], acc[nh][1]);
        *(float2*)(out + (size_t)row1 * NROW + col) = make_float2(acc[nh][2], acc[nh][3]);
    }
}

extern "C" void kernel_launch(void* const* d_in, const int* in_sizes, int n_in,
                              void* d_out, int out_size) {
    const float* x      = (const float*)d_in[0];
    const float* blocks = (const float*)d_in[1];
    float* out = (float*)d_out;

    cudaFuncSetAttribute(block_diag_hmma,
                         cudaFuncAttributeMaxDynamicSharedMemorySize, SMEM_BYTES);
    block_diag_hmma<<<256, 256, SMEM_BYTES>>>(x, blocks, out);
}

// round 8
// speedup vs baseline: 1.1510x; 1.1510x over previous
#include <cuda_runtime.h>
#include <cuda_bf16.h>
#include <cstdint>

// out[64,8192] = x[64,8192] @ blockdiag(blocks), 32 diagonal 256x256 blocks.
// Grid 128 = 32 blocks x 4 col-chunks of 64. Per CTA:
//   out[0:64, col0:col0+64] = x[0:64, k0:k0+256] @ B[k0:k0+256, col0:col0+64]
// bf16 HMMA + 3-term split (xh@Bh + xh@Bl + xl@Bh), K in 4 chunks of 64,
// double-buffered smem, LDG -> compute -> STS -> sync pipeline (R6).
// R8: SEPARATE accumulators per split term -> 6 fully independent HMMA
// chains per warp (was 2 chains with serial 3-deep dependencies per kstep).

#define NROW 8192

#define CHUNK_B  8192            // one bf16 buffer: 64 rows x 128B
#define OFF_AH   0
#define OFF_AL   16384
#define OFF_BH   32768
#define OFF_BL   49152
#define SMEM_BYTES 65536

__device__ __forceinline__ uint32_t smem_u32(const void* p) {
    uint32_t a;
    asm("{ .reg .u64 t; cvta.to.shared.u64 t, %1; cvt.u32.u64 %0, t; }" : "=r"(a) : "l"(p));
    return a;
}
__device__ __forceinline__ void ldsm_x4(uint32_t* r, uint32_t addr) {
    asm volatile("ldmatrix.sync.aligned.m8n8.x4.shared.b16 {%0,%1,%2,%3}, [%4];"
                 : "=r"(r[0]), "=r"(r[1]), "=r"(r[2]), "=r"(r[3]) : "r"(addr));
}
__device__ __forceinline__ void ldsm_x4_t(uint32_t* r, uint32_t addr) {
    asm volatile("ldmatrix.sync.aligned.m8n8.x4.trans.shared.b16 {%0,%1,%2,%3}, [%4];"
                 : "=r"(r[0]), "=r"(r[1]), "=r"(r[2]), "=r"(r[3]) : "r"(addr));
}
__device__ __forceinline__ void mma_bf16(float* d, const uint32_t* a, uint32_t b0, uint32_t b1) {
    asm volatile(
        "mma.sync.aligned.m16n8k16.row.col.f32.bf16.bf16.f32 "
        "{%0,%1,%2,%3}, {%4,%5,%6,%7}, {%8,%9}, {%0,%1,%2,%3};"
        : "+f"(d[0]), "+f"(d[1]), "+f"(d[2]), "+f"(d[3])
        : "r"(a[0]), "r"(a[1]), "r"(a[2]), "r"(a[3]), "r"(b0), "r"(b1));
}
__device__ __forceinline__ void split2(float a, float b, uint32_t& h, uint32_t& l) {
    __nv_bfloat162 hh = __floats2bfloat162_rn(a, b);
    float ra = a - __bfloat162float(hh.x);
    float rb = b - __bfloat162float(hh.y);
    __nv_bfloat162 ll = __floats2bfloat162_rn(ra, rb);
    h = *(uint32_t*)&hh;
    l = *(uint32_t*)&ll;
}

__global__ void __launch_bounds__(512, 1)
block_diag_hmma(const float* __restrict__ x,
                const float* __restrict__ blocks,
                float* __restrict__ out) {
    extern __shared__ char smem[];
    const uint32_t sbase = smem_u32(smem);

    const int tid   = threadIdx.x;
    const int wid   = tid >> 5;
    const int lid   = tid & 31;
    const int bx    = blockIdx.x;
    const int dblk  = bx >> 2;
    const int chunk = bx & 3;
    const int k0    = dblk * 256;
    const int col0  = k0 + chunk * 64;

    const int sm0 = tid >> 4;            // staging row for p=0
    const int sq  = tid & 15;

    auto ldgChunk = [&](int c, float4* ra, float4* rb) {
        const int kg = k0 + c * 64;
        #pragma unroll
        for (int p = 0; p < 2; ++p) {
            int m = sm0 + p * 32;
            ra[p] = *(const float4*)(x + (size_t)m * NROW + kg + sq * 4);
            rb[p] = *(const float4*)(blocks + (size_t)(kg + m) * NROW + col0 + sq * 4);
        }
    };

    auto stsChunk = [&](int buf, const float4* ra, const float4* rb) {
        char* Ah = smem + OFF_AH + buf * CHUNK_B;
        char* Al = smem + OFF_AL + buf * CHUNK_B;
        char* Bh = smem + OFF_BH + buf * CHUNK_B;
        char* Bl = smem + OFF_BL + buf * CHUNK_B;
        uint32_t h01, l01, h23, l23;
        #pragma unroll
        for (int p = 0; p < 2; ++p) {
            int m = sm0 + p * 32;
            uint32_t off = (uint32_t)(m * 128 + (((sq >> 1) ^ (m & 7)) * 16 + (sq & 1) * 8));
            split2(ra[p].x, ra[p].y, h01, l01);
            split2(ra[p].z, ra[p].w, h23, l23);
            *(uint2*)(Ah + off) = make_uint2(h01, h23);
            *(uint2*)(Al + off) = make_uint2(l01, l23);
            split2(rb[p].x, rb[p].y, h01, l01);
            split2(rb[p].z, rb[p].w, h23, l23);
            *(uint2*)(Bh + off) = make_uint2(h01, h23);
            *(uint2*)(Bl + off) = make_uint2(l01, l23);
        }
    };

    // ---- compute setup: warp (wm, wn) -> 16x16 tile ----
    const int wm = wid & 3;
    const int wn = wid >> 2;
    const int m_base = wm * 16;
    const int n_base = wn * 16;

    const int a_row = m_base + (lid & 15);
    const int a_ch  = lid >> 4;
    const int a_rx  = a_row & 7;
    const uint32_t a_rowbase = (uint32_t)(a_row * 128);

    const int b_g   = (wn * 2 + (lid >> 4)) ^ (lid & 7);
    const uint32_t b_base = (uint32_t)((lid & 15) * 128 + b_g * 16);

    // Separate accumulators per split term: 6 independent chains.
    float acc_hh[2][4] = {};
    float acc_hl[2][4] = {};
    float acc_lh[2][4] = {};

    auto computeChunk = [&](int buf) {
        const uint32_t aH = sbase + OFF_AH + buf * CHUNK_B;
        const uint32_t aL = sbase + OFF_AL + buf * CHUNK_B;
        const uint32_t bH = sbase + OFF_BH + buf * CHUNK_B;
        const uint32_t bL = sbase + OFF_BL + buf * CHUNK_B;
        uint32_t ah[4], al[4], bh[4], bl[4];
        #pragma unroll
        for (int ks = 0; ks < 4; ++ks) {
            uint32_t a_off = a_rowbase + (uint32_t)((((ks * 2 + a_ch) ^ a_rx)) * 16);
            uint32_t b_off = b_base + (uint32_t)(ks * 2048);
            ldsm_x4(ah, aH + a_off);
            ldsm_x4(al, aL + a_off);
            ldsm_x4_t(bh, bH + b_off);
            ldsm_x4_t(bl, bL + b_off);
            // 6 independent HMMAs (distinct accumulators)
            mma_bf16(acc_hh[0], ah, bh[0], bh[1]);
            mma_bf16(acc_hl[0], ah, bl[0], bl[1]);
            mma_bf16(acc_lh[0], al, bh[0], bh[1]);
            mma_bf16(acc_hh[1], ah, bh[2], bh[3]);
            mma_bf16(acc_hl[1], ah, bl[2], bl[3]);
            mma_bf16(acc_lh[1], al, bh[2], bh[3]);
        }
    };

    // ---- pipeline: LDG -> compute -> STS -> sync ----
    float4 rA[2][2], rB[2][2];
    ldgChunk(0, rA[0], rB[0]);
    stsChunk(0, rA[0], rB[0]);
    ldgChunk(1, rA[1], rB[1]);
    __syncthreads();

    #pragma unroll
    for (int c = 0; c < 4; ++c) {
        if (c < 2) ldgChunk(c + 2, rA[c & 1], rB[c & 1]);
        computeChunk(c & 1);
        if (c < 3) {
            stsChunk((c + 1) & 1, rA[(c + 1) & 1], rB[(c + 1) & 1]);
            __syncthreads();
        }
    }

    // ---- epilogue: combine terms, store ----
    const int grp = lid >> 2;
    const int tc  = lid & 3;
    const int row0 = m_base + grp;
    const int row1 = row0 + 8;
    #pragma unroll
    for (int nh = 0; nh < 2; ++nh) {
        float v0 = acc_hh[nh][0] + acc_hl[nh][0] + acc_lh[nh][0];
        float v1 = acc_hh[nh][1] + acc_hl[nh][1] + acc_lh[nh][1];
        float v2 = acc_hh[nh][2] + acc_hl[nh][2] + acc_lh[nh][2];
        float v3 = acc_hh[nh][3] + acc_hl[nh][3] + acc_lh[nh][3];
        int col = col0 + n_base + nh * 8 + tc * 2;
        *(float2*)(out + (size_t)row0 * NROW + col) = make_float2(v0, v1);
        *(float2*)(out + (size_t)row1 * NROW + col) = make_float2(v2, v3);
    }
}

extern "C" void kernel_launch(void* const* d_in, const int* in_sizes, int n_in,
                              void* d_out, int out_size) {
    const float* x      = (const float*)d_in[0];
    const float* blocks = (const float*)d_in[1];
    float* out = (float*)d_out;

    cudaFuncSetAttribute(block_diag_hmma,
                         cudaFuncAttributeMaxDynamicSharedMemorySize, SMEM_BYTES);
    block_diag_hmma<<<128, 512, SMEM_BYTES>>>(x, blocks, out);
}

// round 9
// speedup vs baseline: 1.2657x; 1.0996x over previous
#include <cuda_runtime.h>
#include <cuda_fp16.h>
#include <cstdint>

// out[64,8192] = x[64,8192] @ blockdiag(blocks), 32 diagonal 256x256 blocks.
// Grid 128 = 32 blocks x 4 col-chunks of 64. Per CTA:
//   out[0:64, col0:col0+64] = x[0:64, k0:k0+256] @ B[k0:k0+256, col0:col0+64]
//
// R9: fp16 HMMA, 2-term split: out ~= xh@Bh + xl@Bh  (x = xh + xl in fp16;
// B rounded once to fp16 -> dropped x@Bl ~ 2^-12 rel, ~3e-4 aggregate).
// fp32 chunks staged via cp.async into smem; convert reads LDS, writes
// swizzled fp16 tiles; K pipelined in 4 chunks of 64, double-buffered.

#define NROW 8192

#define OFF_AH 0                 // [2] x 8192
#define OFF_AL 16384             // [2] x 8192
#define OFF_BH 32768             // [2] x 8192
#define OFF_FA 49152             // [2] x 16384 (fp32 A chunk)
#define OFF_FB 81920             // [2] x 16384 (fp32 B chunk)
#define SMEM_BYTES 114688

__device__ __forceinline__ uint32_t smem_u32(const void* p) {
    uint32_t a;
    asm("{ .reg .u64 t; cvta.to.shared.u64 t, %1; cvt.u32.u64 %0, t; }" : "=r"(a) : "l"(p));
    return a;
}
__device__ __forceinline__ void cp_async16(uint32_t s, const void* g) {
    asm volatile("cp.async.cg.shared.global [%0], [%1], 16;" :: "r"(s), "l"(g));
}
__device__ __forceinline__ void ldsm_x4(uint32_t* r, uint32_t addr) {
    asm volatile("ldmatrix.sync.aligned.m8n8.x4.shared.b16 {%0,%1,%2,%3}, [%4];"
                 : "=r"(r[0]), "=r"(r[1]), "=r"(r[2]), "=r"(r[3]) : "r"(addr));
}
__device__ __forceinline__ void ldsm_x4_t(uint32_t* r, uint32_t addr) {
    asm volatile("ldmatrix.sync.aligned.m8n8.x4.trans.shared.b16 {%0,%1,%2,%3}, [%4];"
                 : "=r"(r[0]), "=r"(r[1]), "=r"(r[2]), "=r"(r[3]) : "r"(addr));
}
__device__ __forceinline__ void mma_f16(float* d, const uint32_t* a, uint32_t b0, uint32_t b1) {
    asm volatile(
        "mma.sync.aligned.m16n8k16.row.col.f32.f16.f16.f32 "
        "{%0,%1,%2,%3}, {%4,%5,%6,%7}, {%8,%9}, {%0,%1,%2,%3};"
        : "+f"(d[0]), "+f"(d[1]), "+f"(d[2]), "+f"(d[3])
        : "r"(a[0]), "r"(a[1]), "r"(a[2]), "r"(a[3]), "r"(b0), "r"(b1));
}
__device__ __forceinline__ uint32_t h2u(__half2 h) { return *(uint32_t*)&h; }

__global__ void __launch_bounds__(512, 1)
block_diag_hmma(const float* __restrict__ x,
                const float* __restrict__ blocks,
                float* __restrict__ out) {
    extern __shared__ char smem[];
    const uint32_t sbase = smem_u32(smem);

    const int tid   = threadIdx.x;
    const int wid   = tid >> 5;
    const int lid   = tid & 31;
    const int bx    = blockIdx.x;
    const int dblk  = bx >> 2;
    const int chunk = bx & 3;
    const int k0    = dblk * 256;
    const int col0  = k0 + chunk * 64;

    const int sm0 = tid >> 4;            // row for p=0 (0..31); p=1 adds 32
    const int sq  = tid & 15;            // float4 index within 64-float row

    // ---- cp.async one 64-k fp32 chunk: A[64][64] + B[64][64] -> F(buf) ----
    auto cpChunk = [&](int c, int buf) {
        const int kg = k0 + c * 64;
        const uint32_t fa = sbase + OFF_FA + buf * 16384;
        const uint32_t fb = sbase + OFF_FB + buf * 16384;
        #pragma unroll
        for (int p = 0; p < 2; ++p) {
            int m = sm0 + p * 32;
            cp_async16(fa + (uint32_t)(m * 256 + sq * 16),
                       x + (size_t)m * NROW + kg + sq * 4);
            cp_async16(fb + (uint32_t)(m * 256 + sq * 16),
                       blocks + (size_t)(kg + m) * NROW + col0 + sq * 4);
        }
        asm volatile("cp.async.commit_group;" ::: "memory");
    };

    // ---- convert chunk c from F(buf) to fp16 tiles H(buf) ----
    auto convChunk = [&](int buf) {
        const char* FA = smem + OFF_FA + buf * 16384;
        const char* FB = smem + OFF_FB + buf * 16384;
        char* Ah = smem + OFF_AH + buf * 8192;
        char* Al = smem + OFF_AL + buf * 8192;
        char* Bh = smem + OFF_BH + buf * 8192;
        #pragma unroll
        for (int p = 0; p < 2; ++p) {
            int m = sm0 + p * 32;
            float4 va = *(const float4*)(FA + m * 256 + sq * 16);
            float4 vb = *(const float4*)(FB + m * 256 + sq * 16);
            uint32_t off = (uint32_t)(m * 128 + (((sq >> 1) ^ (m & 7)) * 16 + (sq & 1) * 8));
            __half2 h01 = __floats2half2_rn(va.x, va.y);
            __half2 h23 = __floats2half2_rn(va.z, va.w);
            __half2 l01 = __floats2half2_rn(va.x - __low2float(h01),
                                            va.y - __high2float(h01));
            __half2 l23 = __floats2half2_rn(va.z - __low2float(h23),
                                            va.w - __high2float(h23));
            *(uint2*)(Ah + off) = make_uint2(h2u(h01), h2u(h23));
            *(uint2*)(Al + off) = make_uint2(h2u(l01), h2u(l23));
            __half2 b01 = __floats2half2_rn(vb.x, vb.y);
            __half2 b23 = __floats2half2_rn(vb.z, vb.w);
            *(uint2*)(Bh + off) = make_uint2(h2u(b01), h2u(b23));
        }
    };

    // ---- compute setup: 16 warps = 4m x 4n, each 16x16 out tile ----
    const int wm = wid & 3;
    const int wn = wid >> 2;
    const int m_base = wm * 16;
    const int n_base = wn * 16;

    const int a_row = m_base + (lid & 15);
    const int a_ch  = lid >> 4;
    const int a_rx  = a_row & 7;
    const uint32_t a_rowbase = (uint32_t)(a_row * 128);

    const int b_g   = (wn * 2 + (lid >> 4)) ^ (lid & 7);
    const uint32_t b_base = (uint32_t)((lid & 15) * 128 + b_g * 16);

    float acc_h[2][4] = {};
    float acc_l[2][4] = {};

    auto computeChunk = [&](int buf) {
        const uint32_t aH = sbase + OFF_AH + buf * 8192;
        const uint32_t aL = sbase + OFF_AL + buf * 8192;
        const uint32_t bH = sbase + OFF_BH + buf * 8192;
        uint32_t ah[4], al[4], bh[4];
        #pragma unroll
        for (int ks = 0; ks < 4; ++ks) {
            uint32_t a_off = a_rowbase + (uint32_t)((((ks * 2 + a_ch) ^ a_rx)) * 16);
            uint32_t b_off = b_base + (uint32_t)(ks * 2048);
            ldsm_x4(ah, aH + a_off);
            ldsm_x4(al, aL + a_off);
            ldsm_x4_t(bh, bH + b_off);
            mma_f16(acc_h[0], ah, bh[0], bh[1]);
            mma_f16(acc_l[0], al, bh[0], bh[1]);
            mma_f16(acc_h[1], ah, bh[2], bh[3]);
            mma_f16(acc_l[1], al, bh[2], bh[3]);
        }
    };

    // ---- pipeline ----
    cpChunk(0, 0);
    cpChunk(1, 1);

    #pragma unroll
    for (int c = 0; c < 4; ++c) {
        if (c < 3) { asm volatile("cp.async.wait_group 1;" ::: "memory"); }
        else       { asm volatile("cp.async.wait_group 0;" ::: "memory"); }
        __syncthreads();                 // F(c&1) visible to all
        convChunk(c & 1);                // F(c&1) -> H(c&1)
        __syncthreads();                 // H(c&1) visible; F(c&1) free
        if (c < 2) cpChunk(c + 2, c & 1);
        computeChunk(c & 1);
    }

    // ---- epilogue: combine terms, store ----
    const int grp = lid >> 2;
    const int tc  = lid & 3;
    const int row0 = m_base + grp;
    const int row1 = row0 + 8;
    #pragma unroll
    for (int nh = 0; nh < 2; ++nh) {
        float v0 = acc_h[nh][0] + acc_l[nh][0];
        float v1 = acc_h[nh][1] + acc_l[nh][1];
        float v2 = acc_h[nh][2] + acc_l[nh][2];
        float v3 = acc_h[nh][3] + acc_l[nh][3];
        int col = col0 + n_base + nh * 8 + tc * 2;
        *(float2*)(out + (size_t)row0 * NROW + col) = make_float2(v0, v1);
        *(float2*)(out + (size_t)row1 * NROW + col) = make_float2(v2, v3);
    }
}

extern "C" void kernel_launch(void* const* d_in, const int* in_sizes, int n_in,
                              void* d_out, int out_size) {
    const float* x      = (const float*)d_in[0];
    const float* blocks = (const float*)d_in[1];
    float* out = (float*)d_out;

    cudaFuncSetAttribute(block_diag_hmma,
                         cudaFuncAttributeMaxDynamicSharedMemorySize, SMEM_BYTES);
    block_diag_hmma<<<128, 512, SMEM_BYTES>>>(x, blocks, out);
}

// round 10
// speedup vs baseline: 1.2704x; 1.0037x over previous
#include <cuda_runtime.h>
#include <cuda_fp16.h>
#include <cstdint>

// out[64,8192] = x[64,8192] @ blockdiag(blocks), 32 diagonal 256x256 blocks.
// Grid 128 = 32 blocks x 4 col-chunks of 64. Per CTA:
//   out[0:64, col0:col0+64] = x[0:64, k0:k0+256] @ B[k0:k0+256, col0:col0+64]
//
// fp16 HMMA, 2-term split: out ~= xh@Bh + xl@Bh (rel_err ~2e-4).
// R10: critical-path restructure.
//   t0: cp.async ALL 4 B chunks (4 groups, no buffer reuse)
//       + LDG x to regs + convert A once (full-K Ah/Al tiles).
//   per chunk: wait_group -> convB -> ONE sync -> compute. No trailing sync.

#define NROW 8192

#define OFF_AH 0          // 32KB: 64 rows x 512B fp16-hi, swizzled
#define OFF_AL 32768      // 32KB: fp16-lo
#define OFF_BH 65536      // 4 chunks x 8KB
#define OFF_FB 98304      // 4 chunks x 16KB fp32 B staging
#define SMEM_BYTES 163840

__device__ __forceinline__ uint32_t smem_u32(const void* p) {
    uint32_t a;
    asm("{ .reg .u64 t; cvta.to.shared.u64 t, %1; cvt.u32.u64 %0, t; }" : "=r"(a) : "l"(p));
    return a;
}
__device__ __forceinline__ void cp_async16(uint32_t s, const void* g) {
    asm volatile("cp.async.cg.shared.global [%0], [%1], 16;" :: "r"(s), "l"(g));
}
__device__ __forceinline__ void ldsm_x4(uint32_t* r, uint32_t addr) {
    asm volatile("ldmatrix.sync.aligned.m8n8.x4.shared.b16 {%0,%1,%2,%3}, [%4];"
                 : "=r"(r[0]), "=r"(r[1]), "=r"(r[2]), "=r"(r[3]) : "r"(addr));
}
__device__ __forceinline__ void ldsm_x4_t(uint32_t* r, uint32_t addr) {
    asm volatile("ldmatrix.sync.aligned.m8n8.x4.trans.shared.b16 {%0,%1,%2,%3}, [%4];"
                 : "=r"(r[0]), "=r"(r[1]), "=r"(r[2]), "=r"(r[3]) : "r"(addr));
}
__device__ __forceinline__ void mma_f16(float* d, const uint32_t* a, uint32_t b0, uint32_t b1) {
    asm volatile(
        "mma.sync.aligned.m16n8k16.row.col.f32.f16.f16.f32 "
        "{%0,%1,%2,%3}, {%4,%5,%6,%7}, {%8,%9}, {%0,%1,%2,%3};"
        : "+f"(d[0]), "+f"(d[1]), "+f"(d[2]), "+f"(d[3])
        : "r"(a[0]), "r"(a[1]), "r"(a[2]), "r"(a[3]), "r"(b0), "r"(b1));
}
__device__ __forceinline__ uint32_t h2u(__half2 h) { return *(uint32_t*)&h; }

__global__ void __launch_bounds__(512, 1)
block_diag_hmma(const float* __restrict__ x,
                const float* __restrict__ blocks,
                float* __restrict__ out) {
    extern __shared__ char smem[];
    const uint32_t sbase = smem_u32(smem);

    const int tid   = threadIdx.x;
    const int wid   = tid >> 5;
    const int lid   = tid & 31;
    const int bx    = blockIdx.x;
    const int dblk  = bx >> 2;
    const int chunk = bx & 3;
    const int k0    = dblk * 256;
    const int col0  = k0 + chunk * 64;

    // ---- 1) issue ALL B chunks via cp.async (4 groups) ----
    {
        const int sm0 = tid >> 4;        // k-row for p=0
        const int sq  = tid & 15;
        #pragma unroll
        for (int c = 0; c < 4; ++c) {
            const int kg = k0 + c * 64;
            const uint32_t fb = sbase + OFF_FB + c * 16384;
            #pragma unroll
            for (int p = 0; p < 2; ++p) {
                int m = sm0 + p * 32;
                cp_async16(fb + (uint32_t)(m * 256 + sq * 16),
                           blocks + (size_t)(kg + m) * NROW + col0 + sq * 4);
            }
            asm volatile("cp.async.commit_group;" ::: "memory");
        }
    }

    // ---- 2) LDG x (full K) to regs, convert A once into Ah/Al ----
    {
        const int m  = tid >> 3;          // 0..63
        const int q0 = tid & 7;           // f4 lane phase
        float4 vx[8];
        #pragma unroll
        for (int p = 0; p < 8; ++p)
            vx[p] = *(const float4*)(x + (size_t)m * NROW + k0 + (q0 + 8 * p) * 4);
        char* Ah = smem + OFF_AH;
        char* Al = smem + OFF_AL;
        const int mrow = m * 512;
        const int mx   = m & 7;
        #pragma unroll
        for (int p = 0; p < 8; ++p) {
            int q = q0 + 8 * p;           // f4 index 0..63 along K
            int g = q >> 1, hh = q & 1;
            uint32_t off = (uint32_t)(mrow + ((g ^ mx) * 16 + hh * 8));
            __half2 h01 = __floats2half2_rn(vx[p].x, vx[p].y);
            __half2 h23 = __floats2half2_rn(vx[p].z, vx[p].w);
            __half2 l01 = __floats2half2_rn(vx[p].x - __low2float(h01),
                                            vx[p].y - __high2float(h01));
            __half2 l23 = __floats2half2_rn(vx[p].z - __low2float(h23),
                                            vx[p].w - __high2float(h23));
            *(uint2*)(Ah + off) = make_uint2(h2u(h01), h2u(h23));
            *(uint2*)(Al + off) = make_uint2(h2u(l01), h2u(l23));
        }
    }

    // ---- compute setup: 16 warps = 4m x 4n, each a 16x16 out tile ----
    const int wm = wid & 3;
    const int wn = wid >> 2;
    const int m_base = wm * 16;
    const int n_base = wn * 16;

    const int a_row = m_base + (lid & 15);
    const int a_ch  = lid >> 4;
    const int a_rx  = a_row & 7;
    const uint32_t a_rowbase = (uint32_t)(a_row * 512);

    const int b_g   = (wn * 2 + (lid >> 4)) ^ (lid & 7);
    const uint32_t b_base = (uint32_t)((lid & 15) * 128 + b_g * 16);

    const int sm0 = tid >> 4;
    const int sq  = tid & 15;

    float acc_h[2][4] = {};
    float acc_l[2][4] = {};

    // ---- 3) per-chunk: wait -> convB -> sync -> compute ----
    #pragma unroll
    for (int c = 0; c < 4; ++c) {
        if      (c == 0) asm volatile("cp.async.wait_group 3;" ::: "memory");
        else if (c == 1) asm volatile("cp.async.wait_group 2;" ::: "memory");
        else if (c == 2) asm volatile("cp.async.wait_group 1;" ::: "memory");
        else             asm volatile("cp.async.wait_group 0;" ::: "memory");

        // convB: F_B(c) fp32 -> Bh(c) fp16 swizzled
        {
            const char* FB = smem + OFF_FB + c * 16384;
            char* Bh = smem + OFF_BH + c * 8192;
            #pragma unroll
            for (int p = 0; p < 2; ++p) {
                int m = sm0 + p * 32;
                float4 vb = *(const float4*)(FB + m * 256 + sq * 16);
                uint32_t off = (uint32_t)(m * 128 + (((sq >> 1) ^ (m & 7)) * 16 + (sq & 1) * 8));
                __half2 b01 = __floats2half2_rn(vb.x, vb.y);
                __half2 b23 = __floats2half2_rn(vb.z, vb.w);
                *(uint2*)(Bh + off) = make_uint2(h2u(b01), h2u(b23));
            }
        }

        __syncthreads();   // Bh(c) (and, at c=0, Ah/Al) visible to all warps

        // compute chunk c
        {
            const uint32_t aH = sbase + OFF_AH;
            const uint32_t aL = sbase + OFF_AL;
            const uint32_t bH = sbase + OFF_BH + c * 8192;
            uint32_t ah[4], al[4], bh[4];
            #pragma unroll
            for (int ks = 0; ks < 4; ++ks) {
                int G = c * 8 + ks * 2 + a_ch;       // global 16B-granule index
                uint32_t a_off = a_rowbase + (uint32_t)((G ^ a_rx) * 16);
                uint32_t b_off = b_base + (uint32_t)(ks * 2048);
                ldsm_x4(ah, aH + a_off);
                ldsm_x4(al, aL + a_off);
                ldsm_x4_t(bh, bH + b_off);
                mma_f16(acc_h[0], ah, bh[0], bh[1]);
                mma_f16(acc_l[0], al, bh[0], bh[1]);
                mma_f16(acc_h[1], ah, bh[2], bh[3]);
                mma_f16(acc_l[1], al, bh[2], bh[3]);
            }
        }
        // no trailing sync: convB(c+1) writes disjoint smem regions
    }

    // ---- epilogue: combine terms, store ----
    const int grp = lid >> 2;
    const int tc  = lid & 3;
    const int row0 = m_base + grp;
    const int row1 = row0 + 8;
    #pragma unroll
    for (int nh = 0; nh < 2; ++nh) {
        float v0 = acc_h[nh][0] + acc_l[nh][0];
        float v1 = acc_h[nh][1] + acc_l[nh][1];
        float v2 = acc_h[nh][2] + acc_l[nh][2];
        float v3 = acc_h[nh][3] + acc_l[nh][3];
        int col = col0 + n_base + nh * 8 + tc * 2;
        *(float2*)(out + (size_t)row0 * NROW + col) = make_float2(v0, v1);
        *(float2*)(out + (size_t)row1 * NROW + col) = make_float2(v2, v3);
    }
}

extern "C" void kernel_launch(void* const* d_in, const int* in_sizes, int n_in,
                              void* d_out, int out_size) {
    const float* x      = (const float*)d_in[0];
    const float* blocks = (const float*)d_in[1];
    float* out = (float*)d_out;

    cudaFuncSetAttribute(block_diag_hmma,
                         cudaFuncAttributeMaxDynamicSharedMemorySize, SMEM_BYTES);
    block_diag_hmma<<<128, 512, SMEM_BYTES>>>(x, blocks, out);
}

// round 11
// speedup vs baseline: 1.3295x; 1.0465x over previous
#include <cuda_runtime.h>
#include <cuda_fp16.h>
#include <cstdint>

// out[64,8192] = x[64,8192] @ blockdiag(blocks), 32 diagonal 256x256 blocks.
// Grid 128 = 32 blocks x 4 col-chunks of 64. Per CTA:
//   out[0:64, col0:col0+64] = x[0:64, k0:k0+256] @ B[k0:k0+256, col0:col0+64]
//
// R11: single-term fp16 HMMA (x, B each rounded once; rel_err ~3e-4 predicted),
// 1024 threads (32 warps = 8/SMSP) for max latency hiding, two-phase:
// stage-all (LDG burst -> cvt -> STS swizzled) -> one sync -> compute-all.
// Smem 64KB: Ah[64][256] fp16 + Bh[256][64] fp16, both xor-swizzled.

#define NROW 8192

#define OFF_AH 0          // 32KB: 64 rows x 512B
#define OFF_BH 32768      // 32KB: 256 rows x 128B
#define SMEM_BYTES 65536

__device__ __forceinline__ uint32_t smem_u32(const void* p) {
    uint32_t a;
    asm("{ .reg .u64 t; cvta.to.shared.u64 t, %1; cvt.u32.u64 %0, t; }" : "=r"(a) : "l"(p));
    return a;
}
__device__ __forceinline__ void ldsm_x4(uint32_t* r, uint32_t addr) {
    asm volatile("ldmatrix.sync.aligned.m8n8.x4.shared.b16 {%0,%1,%2,%3}, [%4];"
                 : "=r"(r[0]), "=r"(r[1]), "=r"(r[2]), "=r"(r[3]) : "r"(addr));
}
__device__ __forceinline__ void ldsm_x2_t(uint32_t& r0, uint32_t& r1, uint32_t addr) {
    asm volatile("ldmatrix.sync.aligned.m8n8.x2.trans.shared.b16 {%0,%1}, [%2];"
                 : "=r"(r0), "=r"(r1) : "r"(addr));
}
__device__ __forceinline__ void mma_f16(float* d, const uint32_t* a, uint32_t b0, uint32_t b1) {
    asm volatile(
        "mma.sync.aligned.m16n8k16.row.col.f32.f16.f16.f32 "
        "{%0,%1,%2,%3}, {%4,%5,%6,%7}, {%8,%9}, {%0,%1,%2,%3};"
        : "+f"(d[0]), "+f"(d[1]), "+f"(d[2]), "+f"(d[3])
        : "r"(a[0]), "r"(a[1]), "r"(a[2]), "r"(a[3]), "r"(b0), "r"(b1));
}
__device__ __forceinline__ uint32_t h2u(__half2 h) { return *(uint32_t*)&h; }

__global__ void __launch_bounds__(1024, 1)
block_diag_hmma(const float* __restrict__ x,
                const float* __restrict__ blocks,
                float* __restrict__ out) {
    extern __shared__ char smem[];
    const uint32_t sbase = smem_u32(smem);

    const int tid   = threadIdx.x;
    const int wid   = tid >> 5;
    const int lid   = tid & 31;
    const int bx    = blockIdx.x;
    const int dblk  = bx >> 2;
    const int chunk = bx & 3;
    const int k0    = dblk * 256;
    const int col0  = k0 + chunk * 64;

    // ================= stage phase =================
    // A: x[64][256] fp32 -> Ah fp16, swizzled 512B rows. 4096 f4 / 1024 thr = 4.
    // B: blocks[256][64] fp32 -> Bh fp16, swizzled 128B rows. 4096 f4 / 1024 thr = 4.
    {
        float4 va[4], vb[4];
        #pragma unroll
        for (int p = 0; p < 4; ++p) {
            int ia = p * 1024 + tid;
            int m  = ia >> 6;             // 0..63
            int q  = ia & 63;             // f4 along K
            va[p] = *(const float4*)(x + (size_t)m * NROW + k0 + q * 4);
            int ib = p * 1024 + tid;
            int k  = ib >> 4;             // 0..255
            int sq = ib & 15;             // f4 along N
            vb[p] = *(const float4*)(blocks + (size_t)(k0 + k) * NROW + col0 + sq * 4);
        }
        char* Ah = smem + OFF_AH;
        char* Bh = smem + OFF_BH;
        #pragma unroll
        for (int p = 0; p < 4; ++p) {
            int ia = p * 1024 + tid;
            int m  = ia >> 6;
            int q  = ia & 63;
            int g = q >> 1, hh = q & 1;
            uint32_t offA = (uint32_t)(m * 512 + ((g ^ (m & 7)) * 16 + hh * 8));
            __half2 a01 = __floats2half2_rn(va[p].x, va[p].y);
            __half2 a23 = __floats2half2_rn(va[p].z, va[p].w);
            *(uint2*)(Ah + offA) = make_uint2(h2u(a01), h2u(a23));

            int ib = p * 1024 + tid;
            int k  = ib >> 4;
            int sq = ib & 15;
            uint32_t offB = (uint32_t)(k * 128 + (((sq >> 1) ^ (k & 7)) * 16 + (sq & 1) * 8));
            __half2 b01 = __floats2half2_rn(vb[p].x, vb[p].y);
            __half2 b23 = __floats2half2_rn(vb[p].z, vb[p].w);
            *(uint2*)(Bh + offB) = make_uint2(h2u(b01), h2u(b23));
        }
    }

    __syncthreads();

    // ================= compute phase =================
    // 32 warps = 4m x 8n; warp tile 16x8; K=256 in 16 ksteps of m16n8k16.
    const int wm = wid & 3;
    const int wn = wid >> 2;              // 0..7
    const int m_base = wm * 16;
    const int n_base = wn * 8;

    const int a_row = m_base + (lid & 15);
    const int a_ch  = lid >> 4;
    const int a_rx  = a_row & 7;
    const uint32_t a_rowbase = sbase + OFF_AH + (uint32_t)(a_row * 512);

    // B (ldsm x2 trans): lane l(0..15) -> row ks*16 + l, granule wn (cols 8wn..8wn+7)
    const uint32_t b_lane = sbase + OFF_BH
        + (uint32_t)((lid & 15) * 128 + ((wn ^ (lid & 7)) * 16));

    float acc[4] = {};
    uint32_t a[4];
    uint32_t b0, b1;

    #pragma unroll
    for (int ks = 0; ks < 16; ++ks) {
        uint32_t a_off = a_rowbase + (uint32_t)((((ks * 2 + a_ch) ^ a_rx)) * 16);
        ldsm_x4(a, a_off);
        ldsm_x2_t(b0, b1, b_lane + (uint32_t)(ks * 2048));
        mma_f16(acc, a, b0, b1);
    }

    // ---- epilogue: warp 16x8 tile ----
    const int grp = lid >> 2;             // 0..7
    const int tc  = lid & 3;
    const int row0 = m_base + grp;
    const int row1 = row0 + 8;
    const int col  = col0 + n_base + tc * 2;
    *(float2*)(out + (size_t)row0 * NROW + col) = make_float2(acc[0], acc[1]);
    *(float2*)(out + (size_t)row1 * NROW + col) = make_float2(acc[2], acc[3]);
}

extern "C" void kernel_launch(void* const* d_in, const int* in_sizes, int n_in,
                              void* d_out, int out_size) {
    const float* x      = (const float*)d_in[0];
    const float* blocks = (const float*)d_in[1];
    float* out = (float*)d_out;

    cudaFuncSetAttribute(block_diag_hmma,
                         cudaFuncAttributeMaxDynamicSharedMemorySize, SMEM_BYTES);
    block_diag_hmma<<<128, 1024, SMEM_BYTES>>>(x, blocks, out);
}